// round 1
// baseline (speedup 1.0000x reference)
#include <cuda_runtime.h>

// ---------------- problem constants (fixed for this dataset) ----------------
#define Zl    384
#define MBr   46
#define DEGc  7
#define NBc   68
#define BEe   (MBr*DEGc)      // 322 base edges
#define NLD   (NBc*Zl)        // 26112 variable nodes
#define MCK   (MBr*Zl)        // 17664 check nodes
#define EDG   (BEe*Zl)        // 123648 edges
#define BATCH 128
#define B4    32              // batch in float4 units
#define KI    8448            // info bits out
#define NIN   25344           // received LLRs per batch row
#define NITER 20
#define LLRMAX 20.0f

// ---------------- static device scratch (no allocations allowed) ------------
__device__ float4   g_mcv[EDG*B4];      // edge messages m_cv   [edge][b4]  63.3MB
__device__ float4   g_x[2][NLD*B4];     // VN totals, double-buffered       26.8MB
__device__ float4   g_lch[NLD*B4];      // internal channel LLR (-clip)     13.4MB
__device__ unsigned g_bec[BEe];         // per base-edge: (c<<10)|shift
__device__ unsigned g_colptr[NBc+1];    // CSR over base columns
__device__ unsigned g_colent[BEe];      // (base_edge<<10)|shift

// ---------------- graph decode + CSR build (cheap, once per launch) ---------
__global__ void k_build(const int* __restrict__ col) {
    int t = threadIdx.x;
    if (t < BEe) {
        int val = col[t * Zl];          // i=0 edge of this base-edge block
        g_bec[t] = ((unsigned)(val / Zl) << 10) | (unsigned)(val % Zl);
    }
    __syncthreads();
    if (t == 0) {
        unsigned cnt[NBc];
        for (int c = 0; c < NBc; c++) cnt[c] = 0;
        for (int e = 0; e < BEe; e++) cnt[g_bec[e] >> 10]++;
        unsigned run = 0;
        for (int c = 0; c < NBc; c++) { g_colptr[c] = run; run += cnt[c]; }
        g_colptr[NBc] = run;
        unsigned pos[NBc];
        for (int c = 0; c < NBc; c++) pos[c] = 0;
        for (int e = 0; e < BEe; e++) {
            unsigned c = g_bec[e] >> 10;
            g_colent[g_colptr[c] + pos[c]++] = ((unsigned)e << 10) | (g_bec[e] & 1023u);
        }
    }
}

// zero the punctured region of g_lch (first 2*Z variable nodes)
__global__ void k_zero() {
    int t = blockIdx.x * blockDim.x + threadIdx.x;   // 384*256 = 98304 = 768*128
    ((float*)g_lch)[t] = 0.0f;
}

// transpose + clip + negate channel LLRs: lch[(768+n)*128+b] = -clip(llr[b*NIN+n])
__global__ void k_lch(const float* __restrict__ llr) {
    __shared__ float tile[32][33];
    int n0 = blockIdx.x * 32, b0 = blockIdx.y * 32;
    int tx = threadIdx.x, ty = threadIdx.y;          // block (32, 8)
    float* lch = (float*)g_lch;
#pragma unroll
    for (int k = 0; k < 4; k++)
        tile[ty + k*8][tx] = llr[(size_t)(b0 + ty + k*8) * NIN + (n0 + tx)];
    __syncthreads();
#pragma unroll
    for (int k = 0; k < 4; k++) {
        float v = tile[tx][ty + k*8];
        v = fminf(fmaxf(v, -LLRMAX), LLRMAX);
        lch[(size_t)(768 + n0 + ty + k*8) * BATCH + (b0 + tx)] = -v;
    }
}

// ---------------- check-node update (min-sum, exclude-self) -----------------
__device__ __forceinline__ void cnproc(const float v[DEGc], float o[DEGc]) {
    float m1 = 1e30f, m2 = 1e30f;
    int idx = 0;
    unsigned sg = 0, par = 0;
#pragma unroll
    for (int d = 0; d < DEGc; d++) {
        float mag = fabsf(v[d]);
        unsigned neg = (v[d] < 0.0f) ? 1u : 0u;
        sg |= neg << d;
        par ^= neg;
        if (mag < m1) { m2 = m1; m1 = mag; idx = d; }   // first-argmin ties
        else          { m2 = fminf(m2, mag); }
    }
#pragma unroll
    for (int d = 0; d < DEGc; d++) {
        float mag = (d == idx) ? m2 : m1;
        unsigned flip = par ^ ((sg >> d) & 1u);
        o[d] = flip ? -mag : mag;
    }
}

__global__ void k_cn(int it) {
    int tid = blockIdx.x * 256 + threadIdx.x;    // MCK*B4 = 565248 = 2208*256
    int b4 = tid & 31;
    int m  = tid >> 5;
    int r  = m / Zl;
    int i  = m - r * Zl;
    const float4* __restrict__ xo = (it == 0) ? g_lch : g_x[(it - 1) & 1];
    int beb   = r * DEGc;
    int base0 = (beb * Zl + i) * B4 + b4;

    float vx[DEGc], vy[DEGc], vz[DEGc], vw[DEGc];
#pragma unroll
    for (int d = 0; d < DEGc; d++) {
        unsigned u = g_bec[beb + d];
        int c  = (int)(u >> 10);
        int sh = (int)(u & 1023u);
        int iv = i + sh; if (iv >= Zl) iv -= Zl;
        float4 x4 = xo[(c * Zl + iv) * B4 + b4];
        float4 mo = make_float4(0.f, 0.f, 0.f, 0.f);
        if (it != 0) mo = g_mcv[base0 + d * (Zl * B4)];
        vx[d] = x4.x - mo.x; vy[d] = x4.y - mo.y;
        vz[d] = x4.z - mo.z; vw[d] = x4.w - mo.w;
    }
    float ox[DEGc], oy[DEGc], oz[DEGc], ow[DEGc];
    cnproc(vx, ox); cnproc(vy, oy); cnproc(vz, oz); cnproc(vw, ow);
#pragma unroll
    for (int d = 0; d < DEGc; d++)
        g_mcv[base0 + d * (Zl * B4)] = make_float4(ox[d], oy[d], oz[d], ow[d]);
}

// ---------------- variable-node total update --------------------------------
__global__ void k_vn(int it) {
    int tid = blockIdx.x * 256 + threadIdx.x;    // NLD*B4 = 835584 = 3264*256
    int b4 = tid & 31;
    int v  = tid >> 5;
    int c  = v / Zl;
    int i  = v - c * Zl;
    float4 acc = g_lch[v * B4 + b4];
    unsigned j0 = g_colptr[c], j1 = g_colptr[c + 1];
    for (unsigned j = j0; j < j1; j++) {
        unsigned u = g_colent[j];
        int be = (int)(u >> 10);
        int sh = (int)(u & 1023u);
        int ic = i - sh; if (ic < 0) ic += Zl;
        float4 t = g_mcv[(be * Zl + ic) * B4 + b4];
        acc.x += t.x; acc.y += t.y; acc.z += t.z; acc.w += t.w;
    }
    g_x[it & 1][v * B4 + b4] = acc;
}

// ---------------- output: out[b*K+n] = -x[n*128+b], n<K ---------------------
__global__ void k_out(float* __restrict__ out) {
    __shared__ float tile[32][33];
    const float* xf = (const float*)g_x[(NITER - 1) & 1];
    int n0 = blockIdx.x * 32, b0 = blockIdx.y * 32;
    int tx = threadIdx.x, ty = threadIdx.y;      // block (32, 8)
#pragma unroll
    for (int k = 0; k < 4; k++)
        tile[ty + k*8][tx] = xf[(size_t)(n0 + ty + k*8) * BATCH + (b0 + tx)];
    __syncthreads();
#pragma unroll
    for (int k = 0; k < 4; k++)
        out[(size_t)(b0 + ty + k*8) * KI + (n0 + tx)] = -tile[tx][ty + k*8];
}

// ---------------- launch ----------------------------------------------------
extern "C" void kernel_launch(void* const* d_in, const int* in_sizes, int n_in,
                              void* d_out, int out_size) {
    const float* llr = (const float*)d_in[0];
    const int*   col = (const int*)d_in[2];

    k_build<<<1, 512>>>(col);
    k_zero<<<384, 256>>>();
    {
        dim3 g(NIN / 32, BATCH / 32), b(32, 8);
        k_lch<<<g, b>>>(llr);
    }
    for (int it = 0; it < NITER; it++) {
        k_cn<<<(MCK * B4) / 256, 256>>>(it);
        k_vn<<<(NLD * B4) / 256, 256>>>(it);
    }
    {
        dim3 g(KI / 32, BATCH / 32), b(32, 8);
        k_out<<<g, b>>>((float*)d_out);
    }
}

// round 2
// speedup vs baseline: 1.1922x; 1.1922x over previous
#include <cuda_runtime.h>

// ---------------- problem constants (fixed for this dataset) ----------------
#define Zl    384
#define MBr   46
#define DEGc  7
#define NBc   68
#define BEe   (MBr*DEGc)      // 322 base edges
#define NLD   (NBc*Zl)        // 26112 variable nodes
#define MCK   (MBr*Zl)        // 17664 check nodes
#define EDG   (BEe*Zl)        // 123648 edges
#define BATCH 128
#define B4    32              // batch in float4 units
#define KI    8448            // info bits out
#define NIN   25344           // received LLRs per batch row
#define NITER 20
#define LLRMAX 20.0f

// ---------------- static device scratch (no allocations allowed) ------------
__device__ float4   g_mcv[EDG*B4];      // edge messages m_cv   [edge][b4]  63.3MB
__device__ float4   g_x[NLD*B4];        // VN totals                        13.4MB
__device__ float4   g_lch[NLD*B4];      // internal channel LLR (-clip)     13.4MB
__device__ unsigned g_bec[BEe];         // per base-edge: (c<<10)|shift
__device__ unsigned g_colptr[NBc+1];    // CSR over base columns
__device__ unsigned g_colent[BEe];      // (base_edge<<10)|shift

// ---------------- graph decode + CSR build (cheap, once per launch) ---------
__global__ void k_build(const int* __restrict__ col) {
    int t = threadIdx.x;
    if (t < BEe) {
        int val = col[t * Zl];          // i=0 edge of this base-edge block
        g_bec[t] = ((unsigned)(val / Zl) << 10) | (unsigned)(val % Zl);
    }
    __syncthreads();
    if (t == 0) {
        unsigned cnt[NBc];
        for (int c = 0; c < NBc; c++) cnt[c] = 0;
        for (int e = 0; e < BEe; e++) cnt[g_bec[e] >> 10]++;
        unsigned run = 0;
        for (int c = 0; c < NBc; c++) { g_colptr[c] = run; run += cnt[c]; }
        g_colptr[NBc] = run;
        unsigned pos[NBc];
        for (int c = 0; c < NBc; c++) pos[c] = 0;
        for (int e = 0; e < BEe; e++) {
            unsigned c = g_bec[e] >> 10;
            g_colent[g_colptr[c] + pos[c]++] = ((unsigned)e << 10) | (g_bec[e] & 1023u);
        }
    }
}

// zero the punctured region of g_lch (first 2*Z variable nodes)
__global__ void k_zero() {
    int t = blockIdx.x * blockDim.x + threadIdx.x;   // 384*256 = 98304 = 768*128
    ((float*)g_lch)[t] = 0.0f;
}

// transpose + clip + negate channel LLRs: lch[(768+n)*128+b] = -clip(llr[b*NIN+n])
__global__ void k_lch(const float* __restrict__ llr) {
    __shared__ float tile[32][33];
    int n0 = blockIdx.x * 32, b0 = blockIdx.y * 32;
    int tx = threadIdx.x, ty = threadIdx.y;          // block (32, 8)
    float* lch = (float*)g_lch;
#pragma unroll
    for (int k = 0; k < 4; k++)
        tile[ty + k*8][tx] = llr[(size_t)(b0 + ty + k*8) * NIN + (n0 + tx)];
    __syncthreads();
#pragma unroll
    for (int k = 0; k < 4; k++) {
        float v = tile[tx][ty + k*8];
        v = fminf(fmaxf(v, -LLRMAX), LLRMAX);
        lch[(size_t)(768 + n0 + ty + k*8) * BATCH + (b0 + tx)] = -v;
    }
}

// ---------------- check-node update (min-sum, exclude-self) -----------------
// Branchless per-component processing. First-argmin tie handling is implicit:
// on a tie, m2 == m1, so (mag==m1 ? m2 : m1) matches the reference exactly.
#define CNCOMP(F)                                                              \
    {                                                                          \
        float m1 = fabsf(v[0].F), m2 = 1e30f;                                  \
        unsigned par = __float_as_uint(v[0].F);                                \
        _Pragma("unroll")                                                      \
        for (int d = 1; d < DEGc; d++) {                                       \
            float mag = fabsf(v[d].F);                                         \
            m2 = fminf(m2, fmaxf(m1, mag));                                    \
            m1 = fminf(m1, mag);                                               \
            par ^= __float_as_uint(v[d].F);                                    \
        }                                                                      \
        par &= 0x80000000u;                                                    \
        _Pragma("unroll")                                                      \
        for (int d = 0; d < DEGc; d++) {                                       \
            unsigned bits = __float_as_uint(v[d].F);                           \
            float mag = fabsf(v[d].F);                                         \
            float sel = (mag == m1) ? m2 : m1;                                 \
            unsigned s = (par ^ bits) & 0x80000000u;                           \
            v[d].F = __uint_as_float(__float_as_uint(sel) | s);                \
        }                                                                      \
    }

__global__ void __launch_bounds__(256, 5) k_cn(int it) {
    int tid = blockIdx.x * 256 + threadIdx.x;    // MCK*B4 = 565248 = 2208*256
    int b4 = tid & 31;                           // lane = batch slot
    int m  = tid >> 5;                           // check index (warp-uniform)
    int r  = m / Zl;
    int i  = m - r * Zl;
    const float4* __restrict__ xo = (it == 0) ? g_lch : g_x;
    int beb   = r * DEGc;
    int base0 = (beb * Zl + i) * B4 + b4;

    float4 v[DEGc];
#pragma unroll
    for (int d = 0; d < DEGc; d++) {
        unsigned u = g_bec[beb + d];
        int c  = (int)(u >> 10);
        int sh = (int)(u & 1023u);
        int iv = i + sh; if (iv >= Zl) iv -= Zl;
        float4 x4 = __ldg(&xo[(c * Zl + iv) * B4 + b4]);
        if (it != 0) {
            float4 mo = g_mcv[base0 + d * (Zl * B4)];
            x4.x -= mo.x; x4.y -= mo.y; x4.z -= mo.z; x4.w -= mo.w;
        }
        v[d] = x4;
    }

    CNCOMP(x) CNCOMP(y) CNCOMP(z) CNCOMP(w)

#pragma unroll
    for (int d = 0; d < DEGc; d++)
        g_mcv[base0 + d * (Zl * B4)] = v[d];
}

// ---------------- variable-node total update --------------------------------
__global__ void __launch_bounds__(256) k_vn() {
    int tid = blockIdx.x * 256 + threadIdx.x;    // NLD*B4 = 835584 = 3264*256
    int b4 = tid & 31;
    int v  = tid >> 5;
    int c  = v / Zl;
    int i  = v - c * Zl;
    float4 acc = g_lch[v * B4 + b4];
    unsigned j0 = g_colptr[c], j1 = g_colptr[c + 1];
    for (unsigned j = j0; j < j1; j++) {
        unsigned u = g_colent[j];
        int be = (int)(u >> 10);
        int sh = (int)(u & 1023u);
        int ic = i - sh; if (ic < 0) ic += Zl;
        float4 t = __ldg(&g_mcv[(be * Zl + ic) * B4 + b4]);
        acc.x += t.x; acc.y += t.y; acc.z += t.z; acc.w += t.w;
    }
    g_x[v * B4 + b4] = acc;
}

// ---------------- output: out[b*K+n] = -x[n*128+b], n<K ---------------------
__global__ void k_out(float* __restrict__ out) {
    __shared__ float tile[32][33];
    const float* xf = (const float*)g_x;
    int n0 = blockIdx.x * 32, b0 = blockIdx.y * 32;
    int tx = threadIdx.x, ty = threadIdx.y;      // block (32, 8)
#pragma unroll
    for (int k = 0; k < 4; k++)
        tile[ty + k*8][tx] = xf[(size_t)(n0 + ty + k*8) * BATCH + (b0 + tx)];
    __syncthreads();
#pragma unroll
    for (int k = 0; k < 4; k++)
        out[(size_t)(b0 + ty + k*8) * KI + (n0 + tx)] = -tile[tx][ty + k*8];
}

// ---------------- launch ----------------------------------------------------
extern "C" void kernel_launch(void* const* d_in, const int* in_sizes, int n_in,
                              void* d_out, int out_size) {
    const float* llr = (const float*)d_in[0];
    const int*   col = (const int*)d_in[2];

    k_build<<<1, 512>>>(col);
    k_zero<<<384, 256>>>();
    {
        dim3 g(NIN / 32, BATCH / 32), b(32, 8);
        k_lch<<<g, b>>>(llr);
    }
    for (int it = 0; it < NITER; it++) {
        k_cn<<<(MCK * B4) / 256, 256>>>(it);
        k_vn<<<(NLD * B4) / 256, 256>>>();
    }
    {
        dim3 g(KI / 32, BATCH / 32), b(32, 8);
        k_out<<<g, b>>>((float*)d_out);
    }
}